// round 17
// baseline (speedup 1.0000x reference)
#include <cuda_runtime.h>
#include <cuda_bf16.h>
#include <mma.h>

using namespace nvcuda;

// Problem constants (GatedMessageGcn_3126736191774)
#define RR   1000          // number of relations
#define DD   100           // feature dim
#define MM   2000000       // num_messages (segments)
#define EMAX 16000000      // edges

// Padded GEMM dims for WMMA (16x16x8 tf32 tiles)
#define RRP  1008          // 63 * 16
#define KP   104           // 13 * 8
#define NTILE 63

// ---------------------------------------------------------------------------
// Device scratch (static; no runtime allocation allowed)
// ---------------------------------------------------------------------------
__device__ float g_Apad[RRP * KP];   // zero-padded sender   [1008 x 104]
__device__ float g_Bpad[RRP * KP];   // zero-padded receiver [1008 x 104]
__device__ float g_table[RRP * RRP]; // sigmoid gates, stride 1008 (~4.1 MB)
__device__ float g_denom[MM];        // segment sums, 8 MB (L2-resident)
__device__ int   g_recv[EMAX];       // compacted receiver idx, 64 MB

// ---------------------------------------------------------------------------
// Kernel 0: zero-pad both G matrices into [RRP x KP] staging buffers.
// ---------------------------------------------------------------------------
__global__ void pad_kernel(const float* __restrict__ Gs,
                           const float* __restrict__ Gr) {
    int idx = blockIdx.x * blockDim.x + threadIdx.x;
    if (idx >= RRP * KP) return;
    int row = idx / KP;
    int k   = idx % KP;
    bool in = (row < RR) && (k < DD);
    g_Apad[idx] = in ? Gs[row * DD + k] : 0.0f;
    g_Bpad[idx] = in ? Gr[row * DD + k] : 0.0f;
}

// ---------------------------------------------------------------------------
// Kernel 1: TF32 WMMA GEMM + sigmoid epilogue.
//   Each warp computes one 16x16 output tile:
//     energies = Apad @ Bpad^T  (matrix_a row-major, matrix_b col-major,
//     both ld = KP), 13 k-steps of m16n16k8.
//   No smem, no __syncthreads; operands stream from L2 (~820 KB resident).
// ---------------------------------------------------------------------------
__global__ void wmma_sigmoid_kernel() {
    int warp = (blockIdx.x * blockDim.x + threadIdx.x) >> 5;
    if (warp >= NTILE * NTILE) return;
    int it = warp / NTILE;
    int jt = warp % NTILE;

    wmma::fragment<wmma::accumulator, 16, 16, 8, float> acc;
    wmma::fill_fragment(acc, 0.0f);

    const float* Ap = g_Apad + it * 16 * KP;
    const float* Bp = g_Bpad + jt * 16 * KP;

    #pragma unroll
    for (int k0 = 0; k0 < KP; k0 += 8) {
        wmma::fragment<wmma::matrix_a, 16, 16, 8,
                       wmma::precision::tf32, wmma::row_major> a;
        wmma::fragment<wmma::matrix_b, 16, 16, 8,
                       wmma::precision::tf32, wmma::col_major> b;
        wmma::load_matrix_sync(a, Ap + k0, KP);
        wmma::load_matrix_sync(b, Bp + k0, KP);
        #pragma unroll
        for (int i = 0; i < a.num_elements; i++)
            a.x[i] = wmma::__float_to_tf32(a.x[i]);
        #pragma unroll
        for (int i = 0; i < b.num_elements; i++)
            b.x[i] = wmma::__float_to_tf32(b.x[i]);
        wmma::mma_sync(acc, a, b, acc);
    }

    #pragma unroll
    for (int i = 0; i < acc.num_elements; i++)
        acc.x[i] = 1.0f / (1.0f + __expf(-acc.x[i]));

    wmma::store_matrix_sync(g_table + (it * 16) * RRP + jt * 16, acc,
                            RRP, wmma::mem_row_major);
}

// ---------------------------------------------------------------------------
// Kernel 2 (pass 1): 4 edges/thread (champion config — frozen; table
//   stride is now RRP=1008).
// ---------------------------------------------------------------------------
__global__ void edge_pass1_kernel(const int4* __restrict__ rel4,
                                  const int4* __restrict__ msg4,
                                  float4* __restrict__ gates4,
                                  int E4) {
    int t = blockIdx.x * blockDim.x + threadIdx.x;
    if (t >= E4) return;

    int4 ra = rel4[2 * t];
    int4 rb = rel4[2 * t + 1];
    int4 ma = msg4[2 * t];
    int4 mb = msg4[2 * t + 1];

    float g0 = __ldg(&g_table[ra.x * RRP + ra.y]);
    float g1 = __ldg(&g_table[ra.z * RRP + ra.w]);
    float g2 = __ldg(&g_table[rb.x * RRP + rb.y]);
    float g3 = __ldg(&g_table[rb.z * RRP + rb.w]);

    gates4[t] = make_float4(g0, g1, g2, g3);
    reinterpret_cast<int4*>(g_recv)[t] = make_int4(ma.y, ma.w, mb.y, mb.w);

    atomicAdd(&g_denom[ma.y], g0);   // return unused -> REDG
    atomicAdd(&g_denom[ma.w], g1);
    atomicAdd(&g_denom[mb.y], g2);
    atomicAdd(&g_denom[mb.w], g3);
}

// ---------------------------------------------------------------------------
// Kernel 3 (pass 2): weights = gate / (denom[recv] + 1e-8), 4 edges/thread
// ---------------------------------------------------------------------------
__global__ void edge_pass2_kernel(float4* __restrict__ out4, int E4) {
    int t = blockIdx.x * blockDim.x + threadIdx.x;
    if (t >= E4) return;

    int4   r = reinterpret_cast<const int4*>(g_recv)[t];
    float4 g = out4[t];

    float d0 = __ldg(&g_denom[r.x]);
    float d1 = __ldg(&g_denom[r.y]);
    float d2 = __ldg(&g_denom[r.z]);
    float d3 = __ldg(&g_denom[r.w]);

    out4[t] = make_float4(g.x / (d0 + 1e-8f), g.y / (d1 + 1e-8f),
                          g.z / (d2 + 1e-8f), g.w / (d3 + 1e-8f));
}

// ---------------------------------------------------------------------------
// Scalar tails (E % 4 != 0 safety; E=16M so normally empty)
// ---------------------------------------------------------------------------
__global__ void edge_tail_kernel(const int2* __restrict__ rel,
                                 const int2* __restrict__ msg,
                                 float* __restrict__ gates,
                                 int start, int E) {
    int e = start + blockIdx.x * blockDim.x + threadIdx.x;
    if (e >= E) return;
    int2 rp = rel[e];
    int  rv = msg[e].y;
    float g = __ldg(&g_table[rp.x * RRP + rp.y]);
    gates[e] = g;
    g_recv[e] = rv;
    atomicAdd(&g_denom[rv], g);
}

__global__ void edge_tail2_kernel(float* __restrict__ out,
                                  int start, int E) {
    int e = start + blockIdx.x * blockDim.x + threadIdx.x;
    if (e >= E) return;
    out[e] = out[e] / (__ldg(&g_denom[g_recv[e]]) + 1e-8f);
}

// ---------------------------------------------------------------------------
// Host helper: cached symbol address for memset (defined BEFORE use)
// ---------------------------------------------------------------------------
static void* denom_device_addr() {
    static void* p = nullptr;
    if (!p) cudaGetSymbolAddress(&p, g_denom);
    return p;
}

// ---------------------------------------------------------------------------
// Launch
// ---------------------------------------------------------------------------
extern "C" void kernel_launch(void* const* d_in, const int* in_sizes, int n_in,
                              void* d_out, int out_size) {
    const float* Gs = (const float*)d_in[0];
    const float* Gr = (const float*)d_in[1];
    const int4*  rel4 = (const int4*)d_in[2];
    const int4*  msg4 = (const int4*)d_in[3];
    float* out = (float*)d_out;

    int E  = in_sizes[2] / 2;   // (E,2) index pairs
    int E4 = E / 4;
    int tail = E - E4 * 4;

    // 1. zero denom (graph-capturable async memset)
    cudaMemsetAsync(denom_device_addr(), 0, (size_t)MM * sizeof(float));

    // 2. zero-pad operands, then TF32 WMMA GEMM + sigmoid
    pad_kernel<<<(RRP * KP + 255) / 256, 256>>>(Gs, Gr);
    int nwarps = NTILE * NTILE;                 // 3969 warp-tiles
    int wblk = (nwarps * 32 + 255) / 256;       // 497 blocks of 8 warps
    wmma_sigmoid_kernel<<<wblk, 256>>>();

    // 3. pass 1: gates + segment sum
    int nblk = (E4 + 255) / 256;
    edge_pass1_kernel<<<nblk, 256>>>(rel4, msg4, (float4*)out, E4);
    if (tail) {
        edge_tail_kernel<<<1, 256>>>((const int2*)d_in[2], (const int2*)d_in[3],
                                     out, E4 * 4, E);
    }

    // 4. pass 2: normalize
    edge_pass2_kernel<<<nblk, 256>>>((float4*)out, E4);
    if (tail) {
        edge_tail2_kernel<<<1, 256>>>(out, E4 * 4, E);
    }
}